// round 5
// baseline (speedup 1.0000x reference)
#include <cuda_runtime.h>
#include <math.h>

#define NN 4096
#define CEXP 144.269504089f   /* (1/TAU) * log2(e) */
#define RWIN 0.3725f          /* sqrt(20 / CEXP): exp2 term < 2^-20 beyond */

static __device__ float g_xs[NN + 4];   // preds sorted ascending (+padding)
static __device__ float g_ts[NN + 4];   // target permuted alongside (+padding)
static __device__ float g_y[NN];        // y_sorted
static __device__ float g_ss[NN];       // s = 100*y sorted DESCENDING
static __device__ int   g_sidx[NN];     // original indices of that sort

// ---------------------------------------------------------------------------
// Kernel A: rank-by-count sort of (preds, target) by preds ascending.
// ---------------------------------------------------------------------------
__global__ void __launch_bounds__(256)
rank_scatter_pairs(const float* __restrict__ preds,
                   const float* __restrict__ target) {
    const unsigned FULL = 0xffffffffu;
    __shared__ float sx[NN];
    float4* sx4 = (float4*)sx;
    const float4* p4 = (const float4*)preds;
    for (int i = threadIdx.x; i < NN / 4; i += 256) sx4[i] = p4[i];
    __syncthreads();

    int gw   = blockIdx.x * 8 + (threadIdx.x >> 5);
    int lane = threadIdx.x & 31;
    int row  = gw * 2 + (lane >> 4);
    int q    = lane & 15;
    float xi = sx[row];
    int cnt = 0;
    #pragma unroll 8
    for (int t = 0; t < NN / 64; t++) {
        int j = t * 64 + q * 4;
        float4 v = sx4[j >> 2];
        cnt += (v.x < xi) || (v.x == xi && (j + 0) < row);
        cnt += (v.y < xi) || (v.y == xi && (j + 1) < row);
        cnt += (v.z < xi) || (v.z == xi && (j + 2) < row);
        cnt += (v.w < xi) || (v.w == xi && (j + 3) < row);
    }
    cnt += __shfl_xor_sync(FULL, cnt, 1);
    cnt += __shfl_xor_sync(FULL, cnt, 2);
    cnt += __shfl_xor_sync(FULL, cnt, 4);
    cnt += __shfl_xor_sync(FULL, cnt, 8);
    if (q == 0) { g_xs[cnt] = xi; g_ts[cnt] = target[row]; }
    if (blockIdx.x == 0 && threadIdx.x < 4) {
        g_xs[NN + threadIdx.x] = 1e30f;
        g_ts[NN + threadIdx.x] = 0.0f;
    }
}

// ---------------------------------------------------------------------------
// Kernel B: y_sorted[i] = softmax_j(-(xs_i - x_j)^2/tau) . t_j
// 1024 thr, 32 rows/block, all data staged in smem (search + scan are LDS).
// ---------------------------------------------------------------------------
__global__ void __launch_bounds__(1024)
ysoft_kernel() {
    const unsigned FULL = 0xffffffffu;
    __shared__ float sx[NN + 4];
    __shared__ float st_[NN + 4];
    {
        float4* a = (float4*)sx;
        float4* b = (float4*)st_;
        const float4* ga = (const float4*)g_xs;
        const float4* gb = (const float4*)g_ts;
        for (int i = threadIdx.x; i < (NN + 4) / 4; i += 1024) {
            a[i] = ga[i]; b[i] = gb[i];
        }
    }
    __syncthreads();

    const int lane = threadIdx.x & 31;
    const int warp = threadIdx.x >> 5;
    const int row = blockIdx.x * 32 + warp;
    const float xv = sx[row];

    int lim = 0;
    if (lane < 2) {
        float tgt = (lane == 0) ? (xv - RWIN) : (xv + RWIN);
        int l = 0, r = NN;
        while (l < r) {
            int m = (l + r) >> 1;
            bool go = (lane == 0) ? (sx[m] < tgt) : (sx[m] <= tgt);
            if (go) l = m + 1; else r = m;
        }
        lim = l;
    }
    int lo = __shfl_sync(FULL, lim, 0);
    int hi = __shfl_sync(FULL, lim, 1);

    float se = 0.f, su = 0.f;
    int j0 = (lo & ~3) + lane * 4;
    for (int j = j0; j < hi; j += 128) {
        float4 x4 = *reinterpret_cast<const float4*>(sx + j);
        float4 t4 = *reinterpret_cast<const float4*>(st_ + j);
        float d0 = xv - x4.x, d1 = xv - x4.y, d2 = xv - x4.z, d3 = xv - x4.w;
        float a0 = (d0 * d0) * (-CEXP);
        float a1 = (d1 * d1) * (-CEXP);
        float a2 = (d2 * d2) * (-CEXP);
        float a3 = (d3 * d3) * (-CEXP);
        float e0, e1, e2, e3;
        asm("ex2.approx.f32 %0, %1;" : "=f"(e0) : "f"(a0));
        asm("ex2.approx.f32 %0, %1;" : "=f"(e1) : "f"(a1));
        asm("ex2.approx.f32 %0, %1;" : "=f"(e2) : "f"(a2));
        asm("ex2.approx.f32 %0, %1;" : "=f"(e3) : "f"(a3));
        se += e0 + e1 + e2 + e3;
        su = fmaf(e0, t4.x, su);
        su = fmaf(e1, t4.y, su);
        su = fmaf(e2, t4.z, su);
        su = fmaf(e3, t4.w, su);
    }
    for (int off = 16; off; off >>= 1) {
        se += __shfl_down_sync(FULL, se, off);
        su += __shfl_down_sync(FULL, su, off);
    }
    if (lane == 0) g_y[row] = su / se;
}

// ---------------------------------------------------------------------------
// Kernel D: rank-by-count DESCENDING argsort of y; scatter s=100*y + indices.
// ---------------------------------------------------------------------------
__global__ void __launch_bounds__(256)
rank_scatter_y() {
    const unsigned FULL = 0xffffffffu;
    __shared__ float sy[NN];
    float4* sy4 = (float4*)sy;
    const float4* y4 = (const float4*)g_y;
    for (int i = threadIdx.x; i < NN / 4; i += 256) sy4[i] = y4[i];
    __syncthreads();

    int gw   = blockIdx.x * 8 + (threadIdx.x >> 5);
    int lane = threadIdx.x & 31;
    int row  = gw * 2 + (lane >> 4);
    int q    = lane & 15;
    float yi = sy[row];
    int cnt = 0;
    #pragma unroll 8
    for (int t = 0; t < NN / 64; t++) {
        int j = t * 64 + q * 4;
        float4 v = sy4[j >> 2];
        cnt += (v.x > yi) || (v.x == yi && (j + 0) < row);
        cnt += (v.y > yi) || (v.y == yi && (j + 1) < row);
        cnt += (v.z > yi) || (v.z == yi && (j + 2) < row);
        cnt += (v.w > yi) || (v.w == yi && (j + 3) < row);
    }
    cnt += __shfl_xor_sync(FULL, cnt, 1);
    cnt += __shfl_xor_sync(FULL, cnt, 2);
    cnt += __shfl_xor_sync(FULL, cnt, 4);
    cnt += __shfl_xor_sync(FULL, cnt, 8);
    if (q == 0) { g_ss[cnt] = yi * 100.0f; g_sidx[cnt] = row; }
}

// ---------------------------------------------------------------------------
// Kernel C: soft_rank via isotonic regression. Parallel PAV:
//   element pre-pool round -> up to 10 block-merge rounds (run-merging is a
//   sequence of legal pairwise PAV merges; fixpoint = isotonic solution) ->
//   serial PAV finalizer (near no-op when converged).
// ---------------------------------------------------------------------------
__global__ void __launch_bounds__(1024)
rank_kernel(float* out, int out_size) {
    extern __shared__ char smem_raw[];
    float4* pb     = (float4*)smem_raw;            // NN  (blocks: sum,cnt,start)
    float*  s      = (float*)(pb + NN);            // NN  (desc values; later int flags)
    float*  r      = s + NN;                       // NN  (zc prefix / csum / ranks)
    float*  fmean  = r + NN;                       // NN  (ccnt during rounds)
    int*    idx    = (int*)(fmean + NN);           // NN
    int*    bstart = idx + NN;                     // NN+1 (later gstart)
    int*    fstart = bstart + NN + 1;              // NN+1

    __shared__ int   warpTotI[32];
    __shared__ float warpTotF[32];
    __shared__ float warpTotF2[32];
    __shared__ int   warpOffI[32];
    __shared__ float warpOffF[32];
    __shared__ float warpOffF2[32];
    __shared__ int   s_m, s_nb, s_g;
    __shared__ float s_red[32];

    const unsigned FULL = 0xffffffffu;
    int tid  = threadIdx.x;
    int lane = tid & 31;
    int warp = tid >> 5;
    const int base = tid * 4;

    float4 sv = ((const float4*)g_ss)[tid];
    int4   si = ((const int4*)g_sidx)[tid];
    ((float4*)s)[tid] = sv;
    ((int4*)idx)[tid] = si;
    __syncthreads();

    // ---- element-level pre-pool (round 0 with threshold form) -------------
    float prevv = (tid == 0) ? sv.x : s[base - 1];
    int b0 = (base > 0) ? (prevv - sv.x > 1.0f) : 0;
    int b1 = (sv.x - sv.y > 1.0f);
    int b2 = (sv.y - sv.z > 1.0f);
    int b3 = (sv.z - sv.w > 1.0f);
    int cb = b0 + b1 + b2 + b3;
    float zt = (sv.x + sv.y + sv.z + sv.w) - (float)(4 * NN - 4 * base - 6);

    int ic = cb; float fc = zt;
    for (int off = 1; off < 32; off <<= 1) {
        int   ui = __shfl_up_sync(FULL, ic, off);
        float uf = __shfl_up_sync(FULL, fc, off);
        if (lane >= off) { ic += ui; fc += uf; }
    }
    if (lane == 31) { warpTotI[warp] = ic; warpTotF[warp] = fc; }
    __syncthreads();
    if (warp == 0) {
        int   ti = warpTotI[lane];
        float tf = warpTotF[lane];
        int   vi = ti; float vf = tf;
        for (int off = 1; off < 32; off <<= 1) {
            int   ui = __shfl_up_sync(FULL, vi, off);
            float uf = __shfl_up_sync(FULL, vf, off);
            if (lane >= off) { vi += ui; vf += uf; }
        }
        warpOffI[lane] = vi - ti;
        warpOffF[lane] = vf - tf;
    }
    __syncthreads();
    int   exI = warpOffI[warp] + (ic - cb);
    float exF = warpOffF[warp] + (fc - zt);
    {
        int cc = exI; float zc = exF;
        cc += b0; if (b0) bstart[cc] = base + 0;
        zc += sv.x - (float)(NN - base - 0); r[base + 0] = zc;
        cc += b1; if (b1) bstart[cc] = base + 1;
        zc += sv.y - (float)(NN - base - 1); r[base + 1] = zc;
        cc += b2; if (b2) bstart[cc] = base + 2;
        zc += sv.z - (float)(NN - base - 2); r[base + 2] = zc;
        cc += b3; if (b3) bstart[cc] = base + 3;
        zc += sv.w - (float)(NN - base - 3); r[base + 3] = zc;
        if (tid == 0) bstart[0] = 0;
        if (tid == 1023) { s_m = cc + 1; bstart[cc + 1] = NN; }
    }
    __syncthreads();

    int m = s_m;
    for (int b = tid; b < m; b += 1024) {
        int st_ = bstart[b], en = bstart[b + 1];
        float lo_ = (st_ > 0) ? r[st_ - 1] : 0.f;
        pb[b] = make_float4(r[en - 1] - lo_, (float)(en - st_), (float)st_, 0.f);
    }
    __syncthreads();

    // ---- parallel PAV rounds ----------------------------------------------
    int*   gstart = bstart;   // reuse
    float* csum   = r;        // reuse
    float* ccnt   = fmean;    // reuse
    for (int round = 0; round < 10; round++) {
        int f[4]; float su[4], cn[4];
        int cI = 0; float cS = 0.f, cC = 0.f;
        #pragma unroll
        for (int e = 0; e < 4; e++) {
            int i = base + e;
            if (i < m) {
                float4 cur = pb[i];
                int stf;
                if (i == 0) stf = 1;
                else {
                    float4 prv = pb[i - 1];
                    stf = (prv.x * cur.y > cur.x * prv.y) ? 1 : 0;
                }
                f[e] = stf; su[e] = cur.x; cn[e] = cur.y;
            } else { f[e] = 0; su[e] = 0.f; cn[e] = 0.f; }
            cI += f[e]; cS += su[e]; cC += cn[e];
        }
        int icl = cI; float fsl = cS, fcl = cC;
        for (int off = 1; off < 32; off <<= 1) {
            int   ui = __shfl_up_sync(FULL, icl, off);
            float u1 = __shfl_up_sync(FULL, fsl, off);
            float u2 = __shfl_up_sync(FULL, fcl, off);
            if (lane >= off) { icl += ui; fsl += u1; fcl += u2; }
        }
        if (lane == 31) {
            warpTotI[warp] = icl; warpTotF[warp] = fsl; warpTotF2[warp] = fcl;
        }
        __syncthreads();
        if (warp == 0) {
            int   ti = warpTotI[lane];
            float t1 = warpTotF[lane];
            float t2 = warpTotF2[lane];
            int vi = ti; float v1 = t1, v2 = t2;
            for (int off = 1; off < 32; off <<= 1) {
                int   ui = __shfl_up_sync(FULL, vi, off);
                float w1 = __shfl_up_sync(FULL, v1, off);
                float w2 = __shfl_up_sync(FULL, v2, off);
                if (lane >= off) { vi += ui; v1 += w1; v2 += w2; }
            }
            warpOffI[lane] = vi - ti;
            warpOffF[lane] = v1 - t1;
            warpOffF2[lane] = v2 - t2;
            if (lane == 31) s_g = vi;
        }
        __syncthreads();
        int g = s_g;
        if (g == m) break;   // no violations anywhere: isotonic fixpoint

        int   eI = warpOffI[warp] + (icl - cI);
        float eS = warpOffF[warp] + (fsl - cS);
        float eC = warpOffF2[warp] + (fcl - cC);
        #pragma unroll
        for (int e = 0; e < 4; e++) {
            int i = base + e;
            if (i < m) {
                eI += f[e]; eS += su[e]; eC += cn[e];
                if (f[e]) gstart[eI - 1] = i;
                csum[i] = eS; ccnt[i] = eC;
            }
        }
        if (tid == 0) gstart[g] = m;
        __syncthreads();

        // read phase (registers), then write phase
        float4 nv[4];
        #pragma unroll
        for (int e = 0; e < 4; e++) {
            int j = base + e;
            if (j < g) {
                int st_ = gstart[j], en = gstart[j + 1];
                float slo = (st_ > 0) ? csum[st_ - 1] : 0.f;
                float clo = (st_ > 0) ? ccnt[st_ - 1] : 0.f;
                nv[e] = make_float4(csum[en - 1] - slo, ccnt[en - 1] - clo,
                                    pb[st_].z, 0.f);
            }
        }
        __syncthreads();
        #pragma unroll
        for (int e = 0; e < 4; e++) {
            int j = base + e;
            if (j < g) pb[j] = nv[e];
        }
        __syncthreads();
        m = g;
    }

    // ---- serial PAV finalizer (verifies + writes fstart/fmean) ------------
    if (tid == 0) {
        int sp = 0;
        float4 c0 = pb[0];
        float tsum = c0.x, tcnt = c0.y, tstf = c0.z;
        float4 nxt = (m > 1) ? pb[1] : make_float4(0, 0, 0, 0);
        for (int b = 1; b < m; b++) {
            float4 c = nxt;
            if (b + 1 < m) nxt = pb[b + 1];
            float nsum = c.x, ncnt = c.y, nstf = c.z;
            bool havetop = true;
            while (havetop && tsum * ncnt <= nsum * tcnt) {
                nsum += tsum; ncnt += tcnt; nstf = tstf;
                if (sp > 0) {
                    sp--;
                    float4 tpv = pb[sp];
                    tsum = tpv.x; tcnt = tpv.y; tstf = tpv.z;
                } else {
                    havetop = false;
                }
            }
            if (havetop) {
                pb[sp] = make_float4(tsum, tcnt, tstf, 0.f);
                sp++;
            }
            tsum = nsum; tcnt = ncnt; tstf = nstf;
        }
        for (int q_ = 0; q_ < sp; q_++) {
            float4 v = pb[q_];
            fstart[q_] = (int)v.z;
            fmean[q_]  = v.x / v.y;
        }
        fstart[sp] = (int)tstf;
        fmean[sp]  = tsum / tcnt;
        fstart[sp + 1] = NN;
        s_nb = sp + 1;
    }
    __syncthreads();

    // expand + scatter r[idx[k]] = s[k] - v(block(k))
    int nb = s_nb;
    #pragma unroll
    for (int e = 0; e < 4; e++) {
        int k = base + e;
        int l = 0, h = nb;
        while (l + 1 < h) {
            int mid = (l + h) >> 1;
            if (fstart[mid] <= k) l = mid; else h = mid;
        }
        float sval = (e == 0) ? sv.x : (e == 1) ? sv.y : (e == 2) ? sv.z : sv.w;
        int dst = (e == 0) ? si.x : (e == 1) ? si.y : (e == 2) ? si.z : si.w;
        r[dst] = sval - fmean[l];
    }
    __syncthreads();

    float acc = 0.f;
    for (int i = tid; i < NN - 1; i += 1024) acc += fabsf(r[i + 1] - r[i]);
    for (int off = 16; off; off >>= 1) acc += __shfl_down_sync(FULL, acc, off);
    if (lane == 0) s_red[warp] = acc;
    __syncthreads();
    if (warp == 0) {
        float a2 = s_red[lane];
        for (int off = 16; off; off >>= 1) a2 += __shfl_down_sync(FULL, a2, off);
        if (lane == 0) {
            float xi = 1.0f - 3.0f * a2 / ((float)NN * (float)NN - 1.0f);
            out[0] = -xi;
            if (out_size > 1) out[1] = xi;
        }
    }
}

// ---------------------------------------------------------------------------
extern "C" void kernel_launch(void* const* d_in, const int* in_sizes, int n_in,
                              void* d_out, int out_size) {
    const float* preds  = (const float*)d_in[0];
    const float* target = (const float*)d_in[1];
    float* out = (float*)d_out;

    size_t smem = (size_t)NN * 40 + 8;
    static int configured = 0;
    if (!configured) {
        cudaFuncSetAttribute(rank_kernel,
                             cudaFuncAttributeMaxDynamicSharedMemorySize,
                             (int)smem);
        configured = 1;
    }

    rank_scatter_pairs<<<256, 256>>>(preds, target);
    ysoft_kernel<<<NN / 32, 1024>>>();
    rank_scatter_y<<<256, 256>>>();
    rank_kernel<<<1, 1024, smem>>>(out, out_size);
}

// round 6
// speedup vs baseline: 1.1220x; 1.1220x over previous
#include <cuda_runtime.h>
#include <math.h>

#define NN 4096
#define NBF 128          /* fused kernel blocks; all co-resident (<=148 SMs) */
#define CEXP 144.269504089f   /* (1/TAU) * log2(e) */
#define RWIN 0.3725f          /* sqrt(20 / CEXP): exp2 term < 2^-20 beyond */

static __device__ float g_xs[NN + 4];   // preds sorted ascending (+padding)
static __device__ float g_ts[NN + 4];   // target permuted alongside (+padding)
static __device__ float g_y[NN];        // y_sorted
static __device__ float g_ss[NN];       // s = 100*y sorted DESCENDING
static __device__ int   g_sidx[NN];     // original indices of that sort

static __device__ unsigned g_bar_cnt = 0;
static __device__ unsigned g_bar_gen = 0;

// Generation-based grid barrier; replay-safe (equality test on generation).
__device__ __forceinline__ void grid_barrier() {
    __syncthreads();
    if (threadIdx.x == 0) {
        __threadfence();
        unsigned gen = *((volatile unsigned*)&g_bar_gen);
        unsigned t = atomicAdd(&g_bar_cnt, 1u);
        if (t == NBF - 1u) {
            atomicExch(&g_bar_cnt, 0u);
            __threadfence();
            atomicAdd(&g_bar_gen, 1u);
        } else {
            while (*((volatile unsigned*)&g_bar_gen) == gen) {}
            __threadfence();
        }
    }
    __syncthreads();
}

// ---------------------------------------------------------------------------
// Fused kernel: phase A (sort pairs by preds) -> barrier ->
//               phase B (windowed soft-perm y = P@t) -> barrier ->
//               phase D (descending argsort of y).
// 128 blocks x 1024 threads; one row per warp in every phase (balanced).
// ---------------------------------------------------------------------------
__global__ void __launch_bounds__(1024, 1)
xi_front_kernel(const float* __restrict__ preds,
                const float* __restrict__ target) {
    extern __shared__ char smem_raw[];
    const unsigned FULL = 0xffffffffu;
    const int tid  = threadIdx.x;
    const int lane = tid & 31;
    const int warp = tid >> 5;
    const int row  = blockIdx.x * 32 + warp;   // one row per warp

    // ---------------- Phase A: rank-by-count sort of (preds, target) --------
    {
        float* sx = (float*)smem_raw;
        float4* sx4 = (float4*)sx;
        const float4* p4 = (const float4*)preds;
        sx4[tid] = p4[tid];           // 1024 threads x float4 = NN
        __syncthreads();

        float xi = sx[row];
        int cnt = 0;
        #pragma unroll 8
        for (int t = 0; t < NN / 128; t++) {
            int j = t * 128 + lane * 4;
            float4 v = sx4[j >> 2];
            cnt += (v.x < xi) || (v.x == xi && (j + 0) < row);
            cnt += (v.y < xi) || (v.y == xi && (j + 1) < row);
            cnt += (v.z < xi) || (v.z == xi && (j + 2) < row);
            cnt += (v.w < xi) || (v.w == xi && (j + 3) < row);
        }
        cnt += __shfl_xor_sync(FULL, cnt, 1);
        cnt += __shfl_xor_sync(FULL, cnt, 2);
        cnt += __shfl_xor_sync(FULL, cnt, 4);
        cnt += __shfl_xor_sync(FULL, cnt, 8);
        cnt += __shfl_xor_sync(FULL, cnt, 16);
        if (lane == 0) { g_xs[cnt] = xi; g_ts[cnt] = target[row]; }
        if (blockIdx.x == 0 && tid < 4) {
            g_xs[NN + tid] = 1e30f; g_ts[NN + tid] = 0.0f;
        }
    }
    grid_barrier();

    // ---------------- Phase B: windowed soft-perm  y = P @ t ----------------
    {
        float* sx  = (float*)smem_raw;            // NN+4
        float* st_ = sx + (NN + 4);               // NN+4
        {
            float4* a = (float4*)sx;
            float4* b = (float4*)st_;
            const float4* ga = (const float4*)g_xs;
            const float4* gb = (const float4*)g_ts;
            a[tid] = ga[tid];
            b[tid] = gb[tid];
            if (tid == 0) {
                a[NN / 4] = ga[NN / 4];
                b[NN / 4] = gb[NN / 4];
            }
        }
        __syncthreads();

        const float xv = sx[row];
        int lim = 0;
        if (lane < 2) {
            float tgt = (lane == 0) ? (xv - RWIN) : (xv + RWIN);
            int l = 0, r = NN;
            while (l < r) {
                int m = (l + r) >> 1;
                bool go = (lane == 0) ? (sx[m] < tgt) : (sx[m] <= tgt);
                if (go) l = m + 1; else r = m;
            }
            lim = l;
        }
        int lo = __shfl_sync(FULL, lim, 0);
        int hi = __shfl_sync(FULL, lim, 1);

        float se = 0.f, su = 0.f;
        int j0 = (lo & ~3) + lane * 4;
        for (int j = j0; j < hi; j += 128) {
            float4 x4 = *reinterpret_cast<const float4*>(sx + j);
            float4 t4 = *reinterpret_cast<const float4*>(st_ + j);
            float d0 = xv - x4.x, d1 = xv - x4.y, d2 = xv - x4.z, d3 = xv - x4.w;
            float a0 = (d0 * d0) * (-CEXP);
            float a1 = (d1 * d1) * (-CEXP);
            float a2 = (d2 * d2) * (-CEXP);
            float a3 = (d3 * d3) * (-CEXP);
            float e0, e1, e2, e3;
            asm("ex2.approx.f32 %0, %1;" : "=f"(e0) : "f"(a0));
            asm("ex2.approx.f32 %0, %1;" : "=f"(e1) : "f"(a1));
            asm("ex2.approx.f32 %0, %1;" : "=f"(e2) : "f"(a2));
            asm("ex2.approx.f32 %0, %1;" : "=f"(e3) : "f"(a3));
            se += e0 + e1 + e2 + e3;
            su = fmaf(e0, t4.x, su);
            su = fmaf(e1, t4.y, su);
            su = fmaf(e2, t4.z, su);
            su = fmaf(e3, t4.w, su);
        }
        for (int off = 16; off; off >>= 1) {
            se += __shfl_down_sync(FULL, se, off);
            su += __shfl_down_sync(FULL, su, off);
        }
        if (lane == 0) g_y[row] = su / se;
    }
    grid_barrier();

    // ---------------- Phase D: descending argsort of y ----------------------
    {
        float* sy = (float*)smem_raw;
        float4* sy4 = (float4*)sy;
        const float4* y4 = (const float4*)g_y;
        sy4[tid] = y4[tid];
        __syncthreads();

        float yi = sy[row];
        int cnt = 0;
        #pragma unroll 8
        for (int t = 0; t < NN / 128; t++) {
            int j = t * 128 + lane * 4;
            float4 v = sy4[j >> 2];
            cnt += (v.x > yi) || (v.x == yi && (j + 0) < row);
            cnt += (v.y > yi) || (v.y == yi && (j + 1) < row);
            cnt += (v.z > yi) || (v.z == yi && (j + 2) < row);
            cnt += (v.w > yi) || (v.w == yi && (j + 3) < row);
        }
        cnt += __shfl_xor_sync(FULL, cnt, 1);
        cnt += __shfl_xor_sync(FULL, cnt, 2);
        cnt += __shfl_xor_sync(FULL, cnt, 4);
        cnt += __shfl_xor_sync(FULL, cnt, 8);
        cnt += __shfl_xor_sync(FULL, cnt, 16);
        if (lane == 0) { g_ss[cnt] = yi * 100.0f; g_sidx[cnt] = row; }
    }
}

// ---------------------------------------------------------------------------
// Kernel C (R4 version): soft_rank via PAV + loss. Single block, 1024 thr.
// ---------------------------------------------------------------------------
__global__ void __launch_bounds__(1024)
rank_kernel(float* out, int out_size) {
    extern __shared__ char smem_raw[];
    float4* pb     = (float4*)smem_raw;            // NN  (pre-blocks / stack)
    float*  s      = (float*)(pb + NN);            // NN  (descending)
    float*  r      = s + NN;                       // NN  (zc prefix, then ranks)
    float*  fmean  = r + NN;                       // NN
    int*    idx    = (int*)(fmean + NN);           // NN
    int*    bstart = idx + NN;                     // NN+1
    int*    fstart = bstart + NN + 1;              // NN+1

    __shared__ int   warpTotI[32];
    __shared__ float warpTotF[32];
    __shared__ int   warpOffI[32];
    __shared__ float warpOffF[32];
    __shared__ int   s_m, s_nb;
    __shared__ float s_red[32];

    const unsigned FULL = 0xffffffffu;
    int tid  = threadIdx.x;
    int lane = tid & 31;
    int warp = tid >> 5;
    const int base = tid * 4;

    float4 sv = ((const float4*)g_ss)[tid];
    int4   si = ((const int4*)g_sidx)[tid];
    ((float4*)s)[tid] = sv;
    ((int4*)idx)[tid] = si;
    __syncthreads();

    float prev = (tid == 0) ? sv.x : s[base - 1];
    int b0 = (base > 0) ? (prev - sv.x > 1.0f) : 0;
    int b1 = (sv.x - sv.y > 1.0f);
    int b2 = (sv.y - sv.z > 1.0f);
    int b3 = (sv.z - sv.w > 1.0f);
    int cb = b0 + b1 + b2 + b3;
    float zt = (sv.x + sv.y + sv.z + sv.w) - (float)(4 * NN - 4 * base - 6);

    int ic = cb; float fc = zt;
    for (int off = 1; off < 32; off <<= 1) {
        int   ui = __shfl_up_sync(FULL, ic, off);
        float uf = __shfl_up_sync(FULL, fc, off);
        if (lane >= off) { ic += ui; fc += uf; }
    }
    if (lane == 31) { warpTotI[warp] = ic; warpTotF[warp] = fc; }
    __syncthreads();
    if (warp == 0) {
        int   ti = warpTotI[lane];
        float tf = warpTotF[lane];
        int   vi = ti; float vf = tf;
        for (int off = 1; off < 32; off <<= 1) {
            int   ui = __shfl_up_sync(FULL, vi, off);
            float uf = __shfl_up_sync(FULL, vf, off);
            if (lane >= off) { vi += ui; vf += uf; }
        }
        warpOffI[lane] = vi - ti;
        warpOffF[lane] = vf - tf;
    }
    __syncthreads();
    int   exI = warpOffI[warp] + (ic - cb);
    float exF = warpOffF[warp] + (fc - zt);

    {
        int cc = exI;
        float zc = exF;
        cc += b0; if (b0) bstart[cc] = base + 0;
        zc += sv.x - (float)(NN - base - 0); r[base + 0] = zc;
        cc += b1; if (b1) bstart[cc] = base + 1;
        zc += sv.y - (float)(NN - base - 1); r[base + 1] = zc;
        cc += b2; if (b2) bstart[cc] = base + 2;
        zc += sv.z - (float)(NN - base - 2); r[base + 2] = zc;
        cc += b3; if (b3) bstart[cc] = base + 3;
        zc += sv.w - (float)(NN - base - 3); r[base + 3] = zc;
        if (tid == 0) bstart[0] = 0;
        if (tid == 1023) { s_m = cc + 1; bstart[cc + 1] = NN; }
    }
    __syncthreads();

    int m = s_m;
    for (int b = tid; b < m; b += 1024) {
        int st_ = bstart[b], en = bstart[b + 1];
        float lo_ = (st_ > 0) ? r[st_ - 1] : 0.f;
        pb[b] = make_float4(r[en - 1] - lo_, (float)(en - st_), (float)st_, 0.f);
    }
    __syncthreads();

    if (tid == 0) {
        int sp = 0;
        float4 c0 = pb[0];
        float tsum = c0.x, tcnt = c0.y, tstf = c0.z;
        float4 nxt = (m > 1) ? pb[1] : make_float4(0, 0, 0, 0);
        for (int b = 1; b < m; b++) {
            float4 c = nxt;
            if (b + 1 < m) nxt = pb[b + 1];
            float nsum = c.x, ncnt = c.y, nstf = c.z;
            bool havetop = true;
            while (havetop && tsum * ncnt <= nsum * tcnt) {
                nsum += tsum; ncnt += tcnt; nstf = tstf;
                if (sp > 0) {
                    sp--;
                    float4 tpv = pb[sp];
                    tsum = tpv.x; tcnt = tpv.y; tstf = tpv.z;
                } else {
                    havetop = false;
                }
            }
            if (havetop) {
                pb[sp] = make_float4(tsum, tcnt, tstf, 0.f);
                sp++;
            }
            tsum = nsum; tcnt = ncnt; tstf = nstf;
        }
        for (int q_ = 0; q_ < sp; q_++) {
            float4 v = pb[q_];
            fstart[q_] = (int)v.z;
            fmean[q_]  = v.x / v.y;
        }
        fstart[sp] = (int)tstf;
        fmean[sp]  = tsum / tcnt;
        fstart[sp + 1] = NN;
        s_nb = sp + 1;
    }
    __syncthreads();

    int nb = s_nb;
    #pragma unroll
    for (int e = 0; e < 4; e++) {
        int k = base + e;
        int l = 0, h = nb;
        while (l + 1 < h) {
            int mid = (l + h) >> 1;
            if (fstart[mid] <= k) l = mid; else h = mid;
        }
        float sval = (e == 0) ? sv.x : (e == 1) ? sv.y : (e == 2) ? sv.z : sv.w;
        int dst = (e == 0) ? si.x : (e == 1) ? si.y : (e == 2) ? si.z : si.w;
        r[dst] = sval - fmean[l];
    }
    __syncthreads();

    float acc = 0.f;
    for (int i = tid; i < NN - 1; i += 1024) acc += fabsf(r[i + 1] - r[i]);
    for (int off = 16; off; off >>= 1) acc += __shfl_down_sync(FULL, acc, off);
    if (lane == 0) s_red[warp] = acc;
    __syncthreads();
    if (warp == 0) {
        float a2 = s_red[lane];
        for (int off = 16; off; off >>= 1) a2 += __shfl_down_sync(FULL, a2, off);
        if (lane == 0) {
            float xi = 1.0f - 3.0f * a2 / ((float)NN * (float)NN - 1.0f);
            out[0] = -xi;
            if (out_size > 1) out[1] = xi;
        }
    }
}

// ---------------------------------------------------------------------------
extern "C" void kernel_launch(void* const* d_in, const int* in_sizes, int n_in,
                              void* d_out, int out_size) {
    const float* preds  = (const float*)d_in[0];
    const float* target = (const float*)d_in[1];
    float* out = (float*)d_out;

    size_t smemF = (size_t)(2 * (NN + 4)) * sizeof(float);   // 32,800 B
    size_t smemR = (size_t)NN * 40 + 8;                      // 163,848 B
    static int configured = 0;
    if (!configured) {
        cudaFuncSetAttribute(xi_front_kernel,
                             cudaFuncAttributeMaxDynamicSharedMemorySize,
                             (int)smemF);
        cudaFuncSetAttribute(rank_kernel,
                             cudaFuncAttributeMaxDynamicSharedMemorySize,
                             (int)smemR);
        configured = 1;
    }

    xi_front_kernel<<<NBF, 1024, smemF>>>(preds, target);
    rank_kernel<<<1, 1024, smemR>>>(out, out_size);
}

// round 7
// speedup vs baseline: 1.2897x; 1.1495x over previous
#include <cuda_runtime.h>
#include <math.h>

#define NN 4096
#define CEXP 144.269504089f   /* (1/TAU) * log2(e) */
#define RWIN 0.3725f          /* sqrt(20 / CEXP): exp2 term < 2^-20 beyond */

static __device__ float g_xs[NN + 4];   // preds sorted ascending (+padding)
static __device__ float g_ts[NN + 4];   // target permuted alongside (+padding)
static __device__ float g_y[NN];        // y_sorted
static __device__ float g_ss[NN];       // s = 100*y sorted DESCENDING
static __device__ int   g_sidx[NN];     // original indices of that sort

// ---------------------------------------------------------------------------
// Kernel A: rank-by-count sort of (preds, target) by preds ascending.
// 256 blocks x 256 thr; each warp owns 2 rows; every loaded element is
// compared against BOTH rows (register blocking halves LDS traffic).
// ---------------------------------------------------------------------------
__global__ void __launch_bounds__(256)
rank_scatter_pairs(const float* __restrict__ preds,
                   const float* __restrict__ target) {
    const unsigned FULL = 0xffffffffu;
    __shared__ float sx[NN];
    float4* sx4 = (float4*)sx;
    const float4* p4 = (const float4*)preds;
    for (int i = threadIdx.x; i < NN / 4; i += 256) sx4[i] = p4[i];
    __syncthreads();

    int warp = threadIdx.x >> 5;
    int lane = threadIdx.x & 31;
    int row0 = (blockIdx.x * 8 + warp) * 2;      // this warp's two rows
    int row1 = row0 + 1;
    float x0 = sx[row0];
    float x1 = sx[row1];
    int c0 = 0, c1 = 0;
    #pragma unroll 8
    for (int t = 0; t < NN / 128; t++) {
        int j = t * 128 + lane * 4;
        float4 v = sx4[j >> 2];
        c0 += (v.x < x0) || (v.x == x0 && (j + 0) < row0);
        c0 += (v.y < x0) || (v.y == x0 && (j + 1) < row0);
        c0 += (v.z < x0) || (v.z == x0 && (j + 2) < row0);
        c0 += (v.w < x0) || (v.w == x0 && (j + 3) < row0);
        c1 += (v.x < x1) || (v.x == x1 && (j + 0) < row1);
        c1 += (v.y < x1) || (v.y == x1 && (j + 1) < row1);
        c1 += (v.z < x1) || (v.z == x1 && (j + 2) < row1);
        c1 += (v.w < x1) || (v.w == x1 && (j + 3) < row1);
    }
    #pragma unroll
    for (int off = 16; off; off >>= 1) {
        c0 += __shfl_xor_sync(FULL, c0, off);
        c1 += __shfl_xor_sync(FULL, c1, off);
    }
    if (lane == 0) {
        g_xs[c0] = x0; g_ts[c0] = target[row0];
        g_xs[c1] = x1; g_ts[c1] = target[row1];
    }
    if (blockIdx.x == 0 && threadIdx.x < 4) {
        g_xs[NN + threadIdx.x] = 1e30f;
        g_ts[NN + threadIdx.x] = 0.0f;
    }
}

// ---------------------------------------------------------------------------
// Kernel B: y_sorted[i] = softmax_j(-(xs_i - x_j)^2/tau) . t_j
// 1024 thr, 32 rows/block, all data staged in smem (search + scan are LDS).
// ---------------------------------------------------------------------------
__global__ void __launch_bounds__(1024)
ysoft_kernel() {
    const unsigned FULL = 0xffffffffu;
    __shared__ float sx[NN + 4];
    __shared__ float st_[NN + 4];
    {
        float4* a = (float4*)sx;
        float4* b = (float4*)st_;
        const float4* ga = (const float4*)g_xs;
        const float4* gb = (const float4*)g_ts;
        a[threadIdx.x] = ga[threadIdx.x];
        b[threadIdx.x] = gb[threadIdx.x];
        if (threadIdx.x == 0) {
            a[NN / 4] = ga[NN / 4];
            b[NN / 4] = gb[NN / 4];
        }
    }
    __syncthreads();

    const int lane = threadIdx.x & 31;
    const int warp = threadIdx.x >> 5;
    const int row = blockIdx.x * 32 + warp;
    const float xv = sx[row];

    int lim = 0;
    if (lane < 2) {
        float tgt = (lane == 0) ? (xv - RWIN) : (xv + RWIN);
        int l = 0, r = NN;
        while (l < r) {
            int m = (l + r) >> 1;
            bool go = (lane == 0) ? (sx[m] < tgt) : (sx[m] <= tgt);
            if (go) l = m + 1; else r = m;
        }
        lim = l;
    }
    int lo = __shfl_sync(FULL, lim, 0);
    int hi = __shfl_sync(FULL, lim, 1);

    float se = 0.f, su = 0.f;
    int j0 = (lo & ~3) + lane * 4;
    for (int j = j0; j < hi; j += 128) {
        float4 x4 = *reinterpret_cast<const float4*>(sx + j);
        float4 t4 = *reinterpret_cast<const float4*>(st_ + j);
        float d0 = xv - x4.x, d1 = xv - x4.y, d2 = xv - x4.z, d3 = xv - x4.w;
        float a0 = (d0 * d0) * (-CEXP);
        float a1 = (d1 * d1) * (-CEXP);
        float a2 = (d2 * d2) * (-CEXP);
        float a3 = (d3 * d3) * (-CEXP);
        float e0, e1, e2, e3;
        asm("ex2.approx.f32 %0, %1;" : "=f"(e0) : "f"(a0));
        asm("ex2.approx.f32 %0, %1;" : "=f"(e1) : "f"(a1));
        asm("ex2.approx.f32 %0, %1;" : "=f"(e2) : "f"(a2));
        asm("ex2.approx.f32 %0, %1;" : "=f"(e3) : "f"(a3));
        se += e0 + e1 + e2 + e3;
        su = fmaf(e0, t4.x, su);
        su = fmaf(e1, t4.y, su);
        su = fmaf(e2, t4.z, su);
        su = fmaf(e3, t4.w, su);
    }
    for (int off = 16; off; off >>= 1) {
        se += __shfl_down_sync(FULL, se, off);
        su += __shfl_down_sync(FULL, su, off);
    }
    if (lane == 0) g_y[row] = su / se;
}

// ---------------------------------------------------------------------------
// Kernel D: rank-by-count DESCENDING argsort of y (register-blocked, 2 rows
// per warp); scatter s=100*y + original indices.
// ---------------------------------------------------------------------------
__global__ void __launch_bounds__(256)
rank_scatter_y() {
    const unsigned FULL = 0xffffffffu;
    __shared__ float sy[NN];
    float4* sy4 = (float4*)sy;
    const float4* y4 = (const float4*)g_y;
    for (int i = threadIdx.x; i < NN / 4; i += 256) sy4[i] = y4[i];
    __syncthreads();

    int warp = threadIdx.x >> 5;
    int lane = threadIdx.x & 31;
    int row0 = (blockIdx.x * 8 + warp) * 2;
    int row1 = row0 + 1;
    float y0 = sy[row0];
    float y1 = sy[row1];
    int c0 = 0, c1 = 0;
    #pragma unroll 8
    for (int t = 0; t < NN / 128; t++) {
        int j = t * 128 + lane * 4;
        float4 v = sy4[j >> 2];
        c0 += (v.x > y0) || (v.x == y0 && (j + 0) < row0);
        c0 += (v.y > y0) || (v.y == y0 && (j + 1) < row0);
        c0 += (v.z > y0) || (v.z == y0 && (j + 2) < row0);
        c0 += (v.w > y0) || (v.w == y0 && (j + 3) < row0);
        c1 += (v.x > y1) || (v.x == y1 && (j + 0) < row1);
        c1 += (v.y > y1) || (v.y == y1 && (j + 1) < row1);
        c1 += (v.z > y1) || (v.z == y1 && (j + 2) < row1);
        c1 += (v.w > y1) || (v.w == y1 && (j + 3) < row1);
    }
    #pragma unroll
    for (int off = 16; off; off >>= 1) {
        c0 += __shfl_xor_sync(FULL, c0, off);
        c1 += __shfl_xor_sync(FULL, c1, off);
    }
    if (lane == 0) {
        g_ss[c0] = y0 * 100.0f; g_sidx[c0] = row0;
        g_ss[c1] = y1 * 100.0f; g_sidx[c1] = row1;
    }
}

// ---------------------------------------------------------------------------
// Kernel C (R4 version): soft_rank via PAV + loss. Single block, 1024 thr.
// ---------------------------------------------------------------------------
__global__ void __launch_bounds__(1024)
rank_kernel(float* out, int out_size) {
    extern __shared__ char smem_raw[];
    float4* pb     = (float4*)smem_raw;            // NN  (pre-blocks / stack)
    float*  s      = (float*)(pb + NN);            // NN  (descending)
    float*  r      = s + NN;                       // NN  (zc prefix, then ranks)
    float*  fmean  = r + NN;                       // NN
    int*    idx    = (int*)(fmean + NN);           // NN
    int*    bstart = idx + NN;                     // NN+1
    int*    fstart = bstart + NN + 1;              // NN+1

    __shared__ int   warpTotI[32];
    __shared__ float warpTotF[32];
    __shared__ int   warpOffI[32];
    __shared__ float warpOffF[32];
    __shared__ int   s_m, s_nb;
    __shared__ float s_red[32];

    const unsigned FULL = 0xffffffffu;
    int tid  = threadIdx.x;
    int lane = tid & 31;
    int warp = tid >> 5;
    const int base = tid * 4;

    float4 sv = ((const float4*)g_ss)[tid];
    int4   si = ((const int4*)g_sidx)[tid];
    ((float4*)s)[tid] = sv;
    ((int4*)idx)[tid] = si;
    __syncthreads();

    float prev = (tid == 0) ? sv.x : s[base - 1];
    int b0 = (base > 0) ? (prev - sv.x > 1.0f) : 0;
    int b1 = (sv.x - sv.y > 1.0f);
    int b2 = (sv.y - sv.z > 1.0f);
    int b3 = (sv.z - sv.w > 1.0f);
    int cb = b0 + b1 + b2 + b3;
    float zt = (sv.x + sv.y + sv.z + sv.w) - (float)(4 * NN - 4 * base - 6);

    int ic = cb; float fc = zt;
    for (int off = 1; off < 32; off <<= 1) {
        int   ui = __shfl_up_sync(FULL, ic, off);
        float uf = __shfl_up_sync(FULL, fc, off);
        if (lane >= off) { ic += ui; fc += uf; }
    }
    if (lane == 31) { warpTotI[warp] = ic; warpTotF[warp] = fc; }
    __syncthreads();
    if (warp == 0) {
        int   ti = warpTotI[lane];
        float tf = warpTotF[lane];
        int   vi = ti; float vf = tf;
        for (int off = 1; off < 32; off <<= 1) {
            int   ui = __shfl_up_sync(FULL, vi, off);
            float uf = __shfl_up_sync(FULL, vf, off);
            if (lane >= off) { vi += ui; vf += uf; }
        }
        warpOffI[lane] = vi - ti;
        warpOffF[lane] = vf - tf;
    }
    __syncthreads();
    int   exI = warpOffI[warp] + (ic - cb);
    float exF = warpOffF[warp] + (fc - zt);

    {
        int cc = exI;
        float zc = exF;
        cc += b0; if (b0) bstart[cc] = base + 0;
        zc += sv.x - (float)(NN - base - 0); r[base + 0] = zc;
        cc += b1; if (b1) bstart[cc] = base + 1;
        zc += sv.y - (float)(NN - base - 1); r[base + 1] = zc;
        cc += b2; if (b2) bstart[cc] = base + 2;
        zc += sv.z - (float)(NN - base - 2); r[base + 2] = zc;
        cc += b3; if (b3) bstart[cc] = base + 3;
        zc += sv.w - (float)(NN - base - 3); r[base + 3] = zc;
        if (tid == 0) bstart[0] = 0;
        if (tid == 1023) { s_m = cc + 1; bstart[cc + 1] = NN; }
    }
    __syncthreads();

    int m = s_m;
    for (int b = tid; b < m; b += 1024) {
        int st_ = bstart[b], en = bstart[b + 1];
        float lo_ = (st_ > 0) ? r[st_ - 1] : 0.f;
        pb[b] = make_float4(r[en - 1] - lo_, (float)(en - st_), (float)st_, 0.f);
    }
    __syncthreads();

    if (tid == 0) {
        int sp = 0;
        float4 c0 = pb[0];
        float tsum = c0.x, tcnt = c0.y, tstf = c0.z;
        float4 nxt = (m > 1) ? pb[1] : make_float4(0, 0, 0, 0);
        for (int b = 1; b < m; b++) {
            float4 c = nxt;
            if (b + 1 < m) nxt = pb[b + 1];
            float nsum = c.x, ncnt = c.y, nstf = c.z;
            bool havetop = true;
            while (havetop && tsum * ncnt <= nsum * tcnt) {
                nsum += tsum; ncnt += tcnt; nstf = tstf;
                if (sp > 0) {
                    sp--;
                    float4 tpv = pb[sp];
                    tsum = tpv.x; tcnt = tpv.y; tstf = tpv.z;
                } else {
                    havetop = false;
                }
            }
            if (havetop) {
                pb[sp] = make_float4(tsum, tcnt, tstf, 0.f);
                sp++;
            }
            tsum = nsum; tcnt = ncnt; tstf = nstf;
        }
        for (int q_ = 0; q_ < sp; q_++) {
            float4 v = pb[q_];
            fstart[q_] = (int)v.z;
            fmean[q_]  = v.x / v.y;
        }
        fstart[sp] = (int)tstf;
        fmean[sp]  = tsum / tcnt;
        fstart[sp + 1] = NN;
        s_nb = sp + 1;
    }
    __syncthreads();

    int nb = s_nb;
    #pragma unroll
    for (int e = 0; e < 4; e++) {
        int k = base + e;
        int l = 0, h = nb;
        while (l + 1 < h) {
            int mid = (l + h) >> 1;
            if (fstart[mid] <= k) l = mid; else h = mid;
        }
        float sval = (e == 0) ? sv.x : (e == 1) ? sv.y : (e == 2) ? sv.z : sv.w;
        int dst = (e == 0) ? si.x : (e == 1) ? si.y : (e == 2) ? si.z : si.w;
        r[dst] = sval - fmean[l];
    }
    __syncthreads();

    float acc = 0.f;
    for (int i = tid; i < NN - 1; i += 1024) acc += fabsf(r[i + 1] - r[i]);
    for (int off = 16; off; off >>= 1) acc += __shfl_down_sync(FULL, acc, off);
    if (lane == 0) s_red[warp] = acc;
    __syncthreads();
    if (warp == 0) {
        float a2 = s_red[lane];
        for (int off = 16; off; off >>= 1) a2 += __shfl_down_sync(FULL, a2, off);
        if (lane == 0) {
            float xi = 1.0f - 3.0f * a2 / ((float)NN * (float)NN - 1.0f);
            out[0] = -xi;
            if (out_size > 1) out[1] = xi;
        }
    }
}

// ---------------------------------------------------------------------------
extern "C" void kernel_launch(void* const* d_in, const int* in_sizes, int n_in,
                              void* d_out, int out_size) {
    const float* preds  = (const float*)d_in[0];
    const float* target = (const float*)d_in[1];
    float* out = (float*)d_out;

    size_t smemR = (size_t)NN * 40 + 8;
    static int configured = 0;
    if (!configured) {
        cudaFuncSetAttribute(rank_kernel,
                             cudaFuncAttributeMaxDynamicSharedMemorySize,
                             (int)smemR);
        configured = 1;
    }

    rank_scatter_pairs<<<256, 256>>>(preds, target);
    ysoft_kernel<<<NN / 32, 1024>>>();
    rank_scatter_y<<<256, 256>>>();
    rank_kernel<<<1, 1024, smemR>>>(out, out_size);
}

// round 8
// speedup vs baseline: 1.3904x; 1.0781x over previous
#include <cuda_runtime.h>
#include <math.h>

#define NN 4096
#define CEXP 144.269504089f   /* (1/TAU) * log2(e) */
#define RWIN 0.3725f          /* sqrt(20 / CEXP): exp2 term < 2^-20 beyond */

static __device__ float g_xs[NN + 4];   // preds sorted ascending (+padding)
static __device__ float g_ts[NN + 4];   // target permuted alongside (+padding)
static __device__ float g_y[NN];        // y_sorted
static __device__ float g_ss[NN];       // s = 100*y sorted DESCENDING
static __device__ int   g_sidx[NN];     // original indices of that sort

// ---- PDL primitives --------------------------------------------------------
__device__ __forceinline__ void pdl_wait() {
    asm volatile("griddepcontrol.wait;" ::: "memory");
}
__device__ __forceinline__ void pdl_trigger() {
    asm volatile("griddepcontrol.launch_dependents;" ::: "memory");
}

// ---------------------------------------------------------------------------
// Kernel A: rank-by-count sort of (preds, target) by preds ascending.
// 256 blocks x 256 thr; 2 rows per warp (register-blocked).
// ---------------------------------------------------------------------------
__global__ void __launch_bounds__(256)
rank_scatter_pairs(const float* __restrict__ preds,
                   const float* __restrict__ target) {
    const unsigned FULL = 0xffffffffu;
    __shared__ float sx[NN];
    float4* sx4 = (float4*)sx;
    const float4* p4 = (const float4*)preds;
    for (int i = threadIdx.x; i < NN / 4; i += 256) sx4[i] = p4[i];
    __syncthreads();

    int warp = threadIdx.x >> 5;
    int lane = threadIdx.x & 31;
    int row0 = (blockIdx.x * 8 + warp) * 2;
    int row1 = row0 + 1;
    float x0 = sx[row0];
    float x1 = sx[row1];
    int c0 = 0, c1 = 0;
    #pragma unroll 8
    for (int t = 0; t < NN / 128; t++) {
        int j = t * 128 + lane * 4;
        float4 v = sx4[j >> 2];
        c0 += (v.x < x0) || (v.x == x0 && (j + 0) < row0);
        c0 += (v.y < x0) || (v.y == x0 && (j + 1) < row0);
        c0 += (v.z < x0) || (v.z == x0 && (j + 2) < row0);
        c0 += (v.w < x0) || (v.w == x0 && (j + 3) < row0);
        c1 += (v.x < x1) || (v.x == x1 && (j + 0) < row1);
        c1 += (v.y < x1) || (v.y == x1 && (j + 1) < row1);
        c1 += (v.z < x1) || (v.z == x1 && (j + 2) < row1);
        c1 += (v.w < x1) || (v.w == x1 && (j + 3) < row1);
    }
    #pragma unroll
    for (int off = 16; off; off >>= 1) {
        c0 += __shfl_xor_sync(FULL, c0, off);
        c1 += __shfl_xor_sync(FULL, c1, off);
    }
    if (lane == 0) {
        g_xs[c0] = x0; g_ts[c0] = target[row0];
        g_xs[c1] = x1; g_ts[c1] = target[row1];
    }
    if (blockIdx.x == 0 && threadIdx.x < 4) {
        g_xs[NN + threadIdx.x] = 1e30f;
        g_ts[NN + threadIdx.x] = 0.0f;
    }
    pdl_trigger();
}

// ---------------------------------------------------------------------------
// Kernel B: y_sorted[i] = softmax_j(-(xs_i - x_j)^2/tau) . t_j
// 1024 thr, 32 rows/block, all data staged in smem.
// ---------------------------------------------------------------------------
__global__ void __launch_bounds__(1024)
ysoft_kernel() {
    const unsigned FULL = 0xffffffffu;
    __shared__ float sx[NN + 4];
    __shared__ float st_[NN + 4];
    pdl_wait();
    {
        float4* a = (float4*)sx;
        float4* b = (float4*)st_;
        const float4* ga = (const float4*)g_xs;
        const float4* gb = (const float4*)g_ts;
        a[threadIdx.x] = ga[threadIdx.x];
        b[threadIdx.x] = gb[threadIdx.x];
        if (threadIdx.x == 0) {
            a[NN / 4] = ga[NN / 4];
            b[NN / 4] = gb[NN / 4];
        }
    }
    __syncthreads();

    const int lane = threadIdx.x & 31;
    const int warp = threadIdx.x >> 5;
    const int row = blockIdx.x * 32 + warp;
    const float xv = sx[row];

    int lim = 0;
    if (lane < 2) {
        float tgt = (lane == 0) ? (xv - RWIN) : (xv + RWIN);
        int l = 0, r = NN;
        while (l < r) {
            int m = (l + r) >> 1;
            bool go = (lane == 0) ? (sx[m] < tgt) : (sx[m] <= tgt);
            if (go) l = m + 1; else r = m;
        }
        lim = l;
    }
    int lo = __shfl_sync(FULL, lim, 0);
    int hi = __shfl_sync(FULL, lim, 1);

    float se = 0.f, su = 0.f;
    int j0 = (lo & ~3) + lane * 4;
    for (int j = j0; j < hi; j += 128) {
        float4 x4 = *reinterpret_cast<const float4*>(sx + j);
        float4 t4 = *reinterpret_cast<const float4*>(st_ + j);
        float d0 = xv - x4.x, d1 = xv - x4.y, d2 = xv - x4.z, d3 = xv - x4.w;
        float a0 = (d0 * d0) * (-CEXP);
        float a1 = (d1 * d1) * (-CEXP);
        float a2 = (d2 * d2) * (-CEXP);
        float a3 = (d3 * d3) * (-CEXP);
        float e0, e1, e2, e3;
        asm("ex2.approx.f32 %0, %1;" : "=f"(e0) : "f"(a0));
        asm("ex2.approx.f32 %0, %1;" : "=f"(e1) : "f"(a1));
        asm("ex2.approx.f32 %0, %1;" : "=f"(e2) : "f"(a2));
        asm("ex2.approx.f32 %0, %1;" : "=f"(e3) : "f"(a3));
        se += e0 + e1 + e2 + e3;
        su = fmaf(e0, t4.x, su);
        su = fmaf(e1, t4.y, su);
        su = fmaf(e2, t4.z, su);
        su = fmaf(e3, t4.w, su);
    }
    for (int off = 16; off; off >>= 1) {
        se += __shfl_down_sync(FULL, se, off);
        su += __shfl_down_sync(FULL, su, off);
    }
    if (lane == 0) g_y[row] = su / se;
    pdl_trigger();
}

// ---------------------------------------------------------------------------
// Kernel D: rank-by-count DESCENDING argsort of y (register-blocked).
// ---------------------------------------------------------------------------
__global__ void __launch_bounds__(256)
rank_scatter_y() {
    const unsigned FULL = 0xffffffffu;
    __shared__ float sy[NN];
    pdl_wait();
    float4* sy4 = (float4*)sy;
    const float4* y4 = (const float4*)g_y;
    for (int i = threadIdx.x; i < NN / 4; i += 256) sy4[i] = y4[i];
    __syncthreads();

    int warp = threadIdx.x >> 5;
    int lane = threadIdx.x & 31;
    int row0 = (blockIdx.x * 8 + warp) * 2;
    int row1 = row0 + 1;
    float y0 = sy[row0];
    float y1 = sy[row1];
    int c0 = 0, c1 = 0;
    #pragma unroll 8
    for (int t = 0; t < NN / 128; t++) {
        int j = t * 128 + lane * 4;
        float4 v = sy4[j >> 2];
        c0 += (v.x > y0) || (v.x == y0 && (j + 0) < row0);
        c0 += (v.y > y0) || (v.y == y0 && (j + 1) < row0);
        c0 += (v.z > y0) || (v.z == y0 && (j + 2) < row0);
        c0 += (v.w > y0) || (v.w == y0 && (j + 3) < row0);
        c1 += (v.x > y1) || (v.x == y1 && (j + 0) < row1);
        c1 += (v.y > y1) || (v.y == y1 && (j + 1) < row1);
        c1 += (v.z > y1) || (v.z == y1 && (j + 2) < row1);
        c1 += (v.w > y1) || (v.w == y1 && (j + 3) < row1);
    }
    #pragma unroll
    for (int off = 16; off; off >>= 1) {
        c0 += __shfl_xor_sync(FULL, c0, off);
        c1 += __shfl_xor_sync(FULL, c1, off);
    }
    if (lane == 0) {
        g_ss[c0] = y0 * 100.0f; g_sidx[c0] = row0;
        g_ss[c1] = y1 * 100.0f; g_sidx[c1] = row1;
    }
    pdl_trigger();
}

// ---------------------------------------------------------------------------
// Kernel C: soft_rank via PAV + loss. Single block, 1024 thr.
// ---------------------------------------------------------------------------
__global__ void __launch_bounds__(1024)
rank_kernel(float* out, int out_size) {
    extern __shared__ char smem_raw[];
    float4* pb     = (float4*)smem_raw;            // NN  (pre-blocks / stack)
    float*  s      = (float*)(pb + NN);            // NN  (descending)
    float*  r      = s + NN;                       // NN  (zc prefix, then ranks)
    float*  fmean  = r + NN;                       // NN
    int*    idx    = (int*)(fmean + NN);           // NN
    int*    bstart = idx + NN;                     // NN+1
    int*    fstart = bstart + NN + 1;              // NN+1

    __shared__ int   warpTotI[32];
    __shared__ float warpTotF[32];
    __shared__ int   warpOffI[32];
    __shared__ float warpOffF[32];
    __shared__ int   s_m, s_nb;
    __shared__ float s_red[32];

    const unsigned FULL = 0xffffffffu;
    int tid  = threadIdx.x;
    int lane = tid & 31;
    int warp = tid >> 5;
    const int base = tid * 4;

    pdl_wait();
    float4 sv = ((const float4*)g_ss)[tid];
    int4   si = ((const int4*)g_sidx)[tid];
    ((float4*)s)[tid] = sv;
    ((int4*)idx)[tid] = si;
    __syncthreads();

    float prev = (tid == 0) ? sv.x : s[base - 1];
    int b0 = (base > 0) ? (prev - sv.x > 1.0f) : 0;
    int b1 = (sv.x - sv.y > 1.0f);
    int b2 = (sv.y - sv.z > 1.0f);
    int b3 = (sv.z - sv.w > 1.0f);
    int cb = b0 + b1 + b2 + b3;
    float zt = (sv.x + sv.y + sv.z + sv.w) - (float)(4 * NN - 4 * base - 6);

    int ic = cb; float fc = zt;
    for (int off = 1; off < 32; off <<= 1) {
        int   ui = __shfl_up_sync(FULL, ic, off);
        float uf = __shfl_up_sync(FULL, fc, off);
        if (lane >= off) { ic += ui; fc += uf; }
    }
    if (lane == 31) { warpTotI[warp] = ic; warpTotF[warp] = fc; }
    __syncthreads();
    if (warp == 0) {
        int   ti = warpTotI[lane];
        float tf = warpTotF[lane];
        int   vi = ti; float vf = tf;
        for (int off = 1; off < 32; off <<= 1) {
            int   ui = __shfl_up_sync(FULL, vi, off);
            float uf = __shfl_up_sync(FULL, vf, off);
            if (lane >= off) { vi += ui; vf += uf; }
        }
        warpOffI[lane] = vi - ti;
        warpOffF[lane] = vf - tf;
    }
    __syncthreads();
    int   exI = warpOffI[warp] + (ic - cb);
    float exF = warpOffF[warp] + (fc - zt);

    {
        int cc = exI;
        float zc = exF;
        cc += b0; if (b0) bstart[cc] = base + 0;
        zc += sv.x - (float)(NN - base - 0); r[base + 0] = zc;
        cc += b1; if (b1) bstart[cc] = base + 1;
        zc += sv.y - (float)(NN - base - 1); r[base + 1] = zc;
        cc += b2; if (b2) bstart[cc] = base + 2;
        zc += sv.z - (float)(NN - base - 2); r[base + 2] = zc;
        cc += b3; if (b3) bstart[cc] = base + 3;
        zc += sv.w - (float)(NN - base - 3); r[base + 3] = zc;
        if (tid == 0) bstart[0] = 0;
        if (tid == 1023) { s_m = cc + 1; bstart[cc + 1] = NN; }
    }
    __syncthreads();

    int m = s_m;
    for (int b = tid; b < m; b += 1024) {
        int st_ = bstart[b], en = bstart[b + 1];
        float lo_ = (st_ > 0) ? r[st_ - 1] : 0.f;
        pb[b] = make_float4(r[en - 1] - lo_, (float)(en - st_), (float)st_, 0.f);
    }
    __syncthreads();

    if (tid == 0) {
        int sp = 0;
        float4 c0 = pb[0];
        float tsum = c0.x, tcnt = c0.y, tstf = c0.z;
        float4 nxt = (m > 1) ? pb[1] : make_float4(0, 0, 0, 0);
        for (int b = 1; b < m; b++) {
            float4 c = nxt;
            if (b + 1 < m) nxt = pb[b + 1];
            float nsum = c.x, ncnt = c.y, nstf = c.z;
            bool havetop = true;
            while (havetop && tsum * ncnt <= nsum * tcnt) {
                nsum += tsum; ncnt += tcnt; nstf = tstf;
                if (sp > 0) {
                    sp--;
                    float4 tpv = pb[sp];
                    tsum = tpv.x; tcnt = tpv.y; tstf = tpv.z;
                } else {
                    havetop = false;
                }
            }
            if (havetop) {
                pb[sp] = make_float4(tsum, tcnt, tstf, 0.f);
                sp++;
            }
            tsum = nsum; tcnt = ncnt; tstf = nstf;
        }
        for (int q_ = 0; q_ < sp; q_++) {
            float4 v = pb[q_];
            fstart[q_] = (int)v.z;
            fmean[q_]  = v.x / v.y;
        }
        fstart[sp] = (int)tstf;
        fmean[sp]  = tsum / tcnt;
        fstart[sp + 1] = NN;
        s_nb = sp + 1;
    }
    __syncthreads();

    int nb = s_nb;
    #pragma unroll
    for (int e = 0; e < 4; e++) {
        int k = base + e;
        int l = 0, h = nb;
        while (l + 1 < h) {
            int mid = (l + h) >> 1;
            if (fstart[mid] <= k) l = mid; else h = mid;
        }
        float sval = (e == 0) ? sv.x : (e == 1) ? sv.y : (e == 2) ? sv.z : sv.w;
        int dst = (e == 0) ? si.x : (e == 1) ? si.y : (e == 2) ? si.z : si.w;
        r[dst] = sval - fmean[l];
    }
    __syncthreads();

    float acc = 0.f;
    for (int i = tid; i < NN - 1; i += 1024) acc += fabsf(r[i + 1] - r[i]);
    for (int off = 16; off; off >>= 1) acc += __shfl_down_sync(FULL, acc, off);
    if (lane == 0) s_red[warp] = acc;
    __syncthreads();
    if (warp == 0) {
        float a2 = s_red[lane];
        for (int off = 16; off; off >>= 1) a2 += __shfl_down_sync(FULL, a2, off);
        if (lane == 0) {
            float xi = 1.0f - 3.0f * a2 / ((float)NN * (float)NN - 1.0f);
            out[0] = -xi;
            if (out_size > 1) out[1] = xi;
        }
    }
}

// ---------------------------------------------------------------------------
extern "C" void kernel_launch(void* const* d_in, const int* in_sizes, int n_in,
                              void* d_out, int out_size) {
    const float* preds  = (const float*)d_in[0];
    const float* target = (const float*)d_in[1];
    float* out = (float*)d_out;

    size_t smemR = (size_t)NN * 40 + 8;
    static int configured = 0;
    if (!configured) {
        cudaFuncSetAttribute(rank_kernel,
                             cudaFuncAttributeMaxDynamicSharedMemorySize,
                             (int)smemR);
        configured = 1;
    }

    // node 1: plain launch
    rank_scatter_pairs<<<256, 256>>>(preds, target);

    // nodes 2-4: programmatic dependent launches (overlap launch latency)
    cudaLaunchAttribute attr[1];
    attr[0].id = cudaLaunchAttributeProgrammaticStreamSerialization;
    attr[0].val.programmaticStreamSerializationAllowed = 1;

    {
        cudaLaunchConfig_t cfg = {};
        cfg.gridDim = dim3(NN / 32, 1, 1);
        cfg.blockDim = dim3(1024, 1, 1);
        cfg.dynamicSmemBytes = 0;
        cfg.attrs = attr;
        cfg.numAttrs = 1;
        cudaLaunchKernelEx(&cfg, ysoft_kernel);
    }
    {
        cudaLaunchConfig_t cfg = {};
        cfg.gridDim = dim3(256, 1, 1);
        cfg.blockDim = dim3(256, 1, 1);
        cfg.dynamicSmemBytes = 0;
        cfg.attrs = attr;
        cfg.numAttrs = 1;
        cudaLaunchKernelEx(&cfg, rank_scatter_y);
    }
    {
        cudaLaunchConfig_t cfg = {};
        cfg.gridDim = dim3(1, 1, 1);
        cfg.blockDim = dim3(1024, 1, 1);
        cfg.dynamicSmemBytes = smemR;
        cfg.attrs = attr;
        cfg.numAttrs = 1;
        cudaLaunchKernelEx(&cfg, rank_kernel, out, out_size);
    }
}